// round 4
// baseline (speedup 1.0000x reference)
#include <cuda_runtime.h>
#include <math.h>

// Problem constants
#define NR   2048
#define L    128
#define FGV  2.0f

// Tiling
#define RPB      16                  // rows per chunk
#define THREADS  256
#define WPB      8                   // warps per block
#define BPC      10                  // blocks per chunk (80 warps of work)
#define NCHUNKS  (NR / RPB)          // 128
#define GRID     (BPC * NCHUNKS)     // 1280
#define ROWF     (2 * L)             // interleaved (e,f): 256 floats per row
#define PADF     64                  // overread pad (max idx 311 on last row)

// Per-block partials (overwritten every launch -> deterministic)
__device__ float    g_part[GRID];
__device__ float    g_fpart[GRID];
__device__ unsigned g_ctr = 0;       // wraps to 0 via atomicInc every launch

__global__ __launch_bounds__(THREADS) void loss_k(
        const float* __restrict__ y_true,
        const float* __restrict__ y_pred,
        const float* __restrict__ y_diff,
        const float* __restrict__ wts,
        float* __restrict__ out)
{
    __shared__ float efs[RPB * ROWF + PADF];   // rows of interleaved (e, f)
    __shared__ float redp[WPB];
    __shared__ float redf[WPB];
    __shared__ bool  s_last;

    const int tid  = threadIdx.x;
    const int bx   = blockIdx.x;
    const int nch  = bx / BPC;            // row chunk
    const int bic  = bx - nch * BPC;      // block-in-chunk 0..9
    const int n0   = nch * RPB;
    const int lane = tid & 31;

    // ---- diag weights (k==0 column, both p-planes), one block per chunk ----
    float w0d[4], w1d[4];
    const int c4 = tid & 31;              // column float4-group (valid: 256%32==0)
    if (bic == 0) {
#pragma unroll
        for (int s = 0; s < 4; s++) {
            const int c = 4 * c4 + s;
            w0d[s] = wts[c * L];
            w1d[s] = wts[L * L + c * L];
        }
    }

    // ---- stage e = f*d, f into smem (interleaved); fold diag term + f-sum ----
    float floc  = 0.0f;
    float dpart = 0.0f;
    {
        const float4* yt4 = (const float4*)y_true + (size_t)n0 * (L / 4);
        const float4* yp4 = (const float4*)y_pred + (size_t)n0 * (L / 4);
        const float4* yd4 = (const float4*)y_diff + (size_t)n0 * (L / 4);
#pragma unroll
        for (int it = 0; it < RPB * L / 4 / THREADS; it++) {
            const int idx = tid + it * THREADS;          // which float4 group
            const float4 t = yt4[idx];
            const float4 p = yp4[idx];
            const float4 q = yd4[idx];
            float e[4], f[4];
            e[0] = t.x - p.x; e[1] = t.y - p.y; e[2] = t.z - p.z; e[3] = t.w - p.w;
            f[0] = (fabsf(q.x) > FGV) ? 0.0f : 1.0f;
            f[1] = (fabsf(q.y) > FGV) ? 0.0f : 1.0f;
            f[2] = (fabsf(q.z) > FGV) ? 0.0f : 1.0f;
            f[3] = (fabsf(q.w) > FGV) ? 0.0f : 1.0f;
#pragma unroll
            for (int s = 0; s < 4; s++) {
                e[s] *= f[s];                            // e = f * d
                floc += f[s];
                if (bic == 0)
                    dpart += fabsf(e[s]) * w0d[s] + e[s] * e[s] * w1d[s];
            }
            float4 lo, hi;
            lo.x = e[0]; lo.y = f[0]; lo.z = e[1]; lo.w = f[1];
            hi.x = e[2]; hi.y = f[2]; hi.z = e[3]; hi.w = f[3];
            ((float4*)efs)[2 * idx]     = lo;
            ((float4*)efs)[2 * idx + 1] = hi;
        }
    }
    if (tid < PADF) efs[RPB * ROWF + tid] = 0.0f;        // keep overreads finite/zero
    __syncthreads();

    // ---- warp -> (i-band a, j-quadrant wq); all warps identical work ----
    const int gw = bic * WPB + (tid >> 5);   // 0..79 within chunk
    int a, wq;
    if (gw < 32)      { a = gw >> 2;               wq = gw & 3; }
    else if (gw < 56) { a = 8  + (gw - 32) / 3;    wq = (gw - 32) % 3; }
    else if (gw < 72) { a = 16 + ((gw - 56) >> 1); wq = (gw - 56) & 1; }
    else              { a = 24 + (gw - 72);        wq = 0; }
    const int i0 = 4 * a;                 // 16B-aligned i base
    const int j  = i0 + 32 * wq + lane;   // this lane's j (may be >= L: masked)

    // ---- hot loop: |e_i f_j - e_j f_i| form; 3 LDS + 16 FMA-pipe per r ----
    float S1[4] = {0, 0, 0, 0}, S2[4] = {0, 0, 0, 0};
#pragma unroll
    for (int r = 0; r < RPB; r++) {
        const float* row = efs + r * ROWF;
        const float2 ejf = *(const float2*)(row + 2 * j);      // (e_j, f_j)
        const float4 p01 = *(const float4*)(row + 2 * i0);     // (e0,f0,e1,f1)
        const float4 p23 = *(const float4*)(row + 2 * i0 + 4); // (e2,f2,e3,f3)
        const float ei[4] = { p01.x, p01.z, p23.x, p23.z };
        const float fi[4] = { p01.y, p01.w, p23.y, p23.w };
#pragma unroll
        for (int s = 0; s < 4; s++) {
            const float t = ejf.x * fi[s];
            const float u = fmaf(ei[s], ejf.y, -t);   // = yf * (d_i - d_j)
            S1[s] += fabsf(u);                        // p = 1
            S2[s] = fmaf(u, u, S2[s]);                // p = 2 (yf^2 = yf)
        }
    }

    // ---- epilogue: weights once, invalid slots masked ----
    float part = (bic == 0) ? dpart : 0.0f;
#pragma unroll
    for (int s = 0; s < 4; s++) {
        const int  i     = i0 + s;
        const int  k     = j - i;                 // k>=1 live; k==0 in staging
        const bool valid = (k >= 1) && (j < L);
        const int  kc    = min(max(k, 1), L - 1);
        const float w0 = wts[i * L + kc];
        const float w1 = wts[L * L + i * L + kc];
        part += (valid ? 1.0f : 0.0f) * (w0 * S1[s] + w1 * S2[s]);
    }

    // ---- block reduction -> per-block partial ----
#pragma unroll
    for (int o = 16; o > 0; o >>= 1) {
        part += __shfl_xor_sync(0xffffffffu, part, o);
        floc += __shfl_xor_sync(0xffffffffu, floc, o);
    }
    const int wid = tid >> 5;
    if (lane == 0) { redp[wid] = part; redf[wid] = floc; }
    __syncthreads();
    if (tid == 0) {
        float p = 0.0f, ff = 0.0f;
#pragma unroll
        for (int w = 0; w < WPB; w++) { p += redp[w]; ff += redf[w]; }
        g_part[bx]  = p;
        g_fpart[bx] = ff;
        __threadfence();
        const unsigned old = atomicInc(&g_ctr, GRID - 1);   // wraps each launch
        s_last = (old == GRID - 1);
    }
    __syncthreads();

    // ---- last block finalizes ----
    if (s_last) {
        __threadfence();
        double lp = 0.0;
        float  fp = 0.0f;
        for (int idx = tid; idx < GRID; idx += THREADS) {
            lp += (double)g_part[idx];
            fp += g_fpart[idx];
        }
#pragma unroll
        for (int o = 16; o > 0; o >>= 1) {
            lp += __shfl_xor_sync(0xffffffffu, lp, o);
            fp += __shfl_xor_sync(0xffffffffu, fp, o);
        }
        __shared__ double dred[WPB];
        __shared__ float  fred[WPB];
        if (lane == 0) { dred[wid] = lp; fred[wid] = fp; }
        __syncthreads();
        if (tid == 0) {
            double lt = 0.0; float ft = 0.0f;
#pragma unroll
            for (int w = 0; w < WPB; w++) { lt += dred[w]; ft += fred[w]; }
            // loss/l/(n*mean(f)) == total / sum(f); f-sum counted BPC times
            out[0] = (float)(lt / ((double)ft / (double)BPC));
        }
    }
}

extern "C" void kernel_launch(void* const* d_in, const int* in_sizes, int n_in,
                              void* d_out, int out_size)
{
    const float* y_true  = (const float*)d_in[0];
    const float* y_pred  = (const float*)d_in[1];
    const float* y_diff  = (const float*)d_in[2];
    const float* weights = (const float*)d_in[3];
    loss_k<<<GRID, THREADS>>>(y_true, y_pred, y_diff, weights, (float*)d_out);
}